// round 10
// baseline (speedup 1.0000x reference)
#include <cuda_runtime.h>
#include <cstdint>
#include <float.h>
#include <math.h>

#define BB 4
#define NN 4096
#define CC 128
#define KK 8
#define EVP 4104
#define ITERS 15

__device__ float  g_normA[(size_t)BB*NN*CC];
__device__ float  g_normB[(size_t)BB*NN*CC];
__device__ float  g_E[(size_t)BB*NN*NN];
__device__ float  g_eu[BB*EVP];
__device__ float  g_ev[BB*EVP];
__device__ float  g_part[(size_t)BB*8*NN];
__device__ float  g_lu[BB*NN];
__device__ float  g_lv[BB*NN];
__device__ float  g_logp[(size_t)BB*NN*KK];
__device__ int    g_topi[(size_t)BB*NN*KK];
__device__ float2 g_tpos[(size_t)BB*NN*KK];
__device__ float2 g_disp[(size_t)BB*KK*NN];
__device__ float  g_S[BB*NN];
__device__ float  g_ent[BB*NN];

__device__ __forceinline__ float fexp(float x){
    float t=x*1.44269504088896341f, r=rintf(t);
    float g=fmaf(r,-0.693359375f,x); g=fmaf(r,2.12194440e-4f,g);
    float p=1.9875691500e-4f;
    p=fmaf(p,g,1.3981999507e-3f); p=fmaf(p,g,8.3334519073e-3f);
    p=fmaf(p,g,4.1665795894e-2f); p=fmaf(p,g,1.6666665459e-1f);
    p=fmaf(p,g,5.0000001201e-1f);
    return (fmaf(g*g,p,g)+1.0f)*__int_as_float(((int)r+127)<<23);
}
__device__ __forceinline__ float divrn(float x, float t, float c){
    float q=__fmul_rn(x,c), r=fmaf(-t,q,x); return fmaf(r,c,q);
}
__device__ __forceinline__ float get_eds(const float* du, const float* te){
    float tc=fminf(fmaxf(__ldg(te),0.03f),10.0f);
    return fexp(fminf(fmaxf(__fdiv_rn(__ldg(du),tc),-50.0f),50.0f));
}

// 1) L2 normalize, IEEE sqrt/div
__global__ void k_normalize(const float* __restrict__ fa, const float* __restrict__ fb){
    int w=(blockIdx.x*blockDim.x+threadIdx.x)>>5, l=threadIdx.x&31;
    if(w>=BB*NN) return;
    const float* src=(blockIdx.y?fb:fa)+(size_t)w*CC;
    float* dst=(blockIdx.y?g_normB:g_normA)+(size_t)w*CC;
    float x0=src[l],x1=src[l+32],x2=src[l+64],x3=src[l+96];
    float s=0.f;
    s=fmaf(x0,x0,s); s=fmaf(x1,x1,s); s=fmaf(x2,x2,s); s=fmaf(x3,x3,s);
    #pragma unroll
    for(int o=16;o;o>>=1) s+=__shfl_down_sync(~0u,s,o);
    s=__shfl_sync(~0u,s,0);
    float d=fmaxf(__fsqrt_rn(s),1e-12f);
    dst[l]=__fdiv_rn(x0,d); dst[l+32]=__fdiv_rn(x1,d);
    dst[l+64]=__fdiv_rn(x2,d); dst[l+96]=__fdiv_rn(x3,d);
}

// 2) SGEMM raw=A@B^T; E=exp(clip(raw/temp))
__global__ __launch_bounds__(256,2)
void k_gemm(float* __restrict__ out_raw, const float* __restrict__ tempp){
    int b=blockIdx.z, tm=blockIdx.y*128, tn=blockIdx.x*128;
    __shared__ float As[32][132], Bs[32][132];
    const float* A=g_normA+(size_t)b*NN*CC;
    const float* Bm=g_normB+(size_t)b*NN*CC;
    int tid=threadIdx.x, lr=tid>>3, lc=(tid&7)*4, tx=tid&15, ty=tid>>4;
    float acc[8][8];
    #pragma unroll
    for(int i=0;i<8;i++)
        #pragma unroll
        for(int j=0;j<8;j++) acc[i][j]=0.f;
    for(int k0=0;k0<CC;k0+=32){
        #pragma unroll
        for(int p=0;p<4;p++){
            int r=lr+p*32;
            float4 va=*(const float4*)(A +(size_t)(tm+r)*CC+k0+lc);
            float4 vb=*(const float4*)(Bm+(size_t)(tn+r)*CC+k0+lc);
            As[lc+0][r]=va.x; As[lc+1][r]=va.y; As[lc+2][r]=va.z; As[lc+3][r]=va.w;
            Bs[lc+0][r]=vb.x; Bs[lc+1][r]=vb.y; Bs[lc+2][r]=vb.z; Bs[lc+3][r]=vb.w;
        }
        __syncthreads();
        #pragma unroll
        for(int k=0;k<32;k++){
            float4 a0=*(const float4*)&As[k][ty*8], a1=*(const float4*)&As[k][ty*8+4];
            float4 b0=*(const float4*)&Bs[k][tx*8], b1=*(const float4*)&Bs[k][tx*8+4];
            float a[8]={a0.x,a0.y,a0.z,a0.w,a1.x,a1.y,a1.z,a1.w};
            float bf[8]={b0.x,b0.y,b0.z,b0.w,b1.x,b1.y,b1.z,b1.w};
            #pragma unroll
            for(int i=0;i<8;i++)
                #pragma unroll
                for(int j=0;j<8;j++) acc[i][j]=fmaf(a[i],bf[j],acc[i][j]);
        }
        __syncthreads();
    }
    float tv=__ldg(tempp), c=__frcp_rn(tv);
    #pragma unroll
    for(int i=0;i<8;i++){
        size_t off=((size_t)b*NN+tm+ty*8+i)*NN+tn+tx*8;
        *(float4*)(out_raw+off)  =make_float4(acc[i][0],acc[i][1],acc[i][2],acc[i][3]);
        *(float4*)(out_raw+off+4)=make_float4(acc[i][4],acc[i][5],acc[i][6],acc[i][7]);
        float e[8];
        #pragma unroll
        for(int j=0;j<8;j++){
            float z=fminf(fmaxf(divrn(acc[i][j],tv,c),-50.f),50.f);
            e[j]=fexp(z);
        }
        *(float4*)(g_E+off)  =make_float4(e[0],e[1],e[2],e[3]);
        *(float4*)(g_E+off+4)=make_float4(e[4],e[5],e[6],e[7]);
    }
}

// 3) Sinkhorn, exp domain — batch-outer loop keeps one batch's E (67MB) L2-resident
__global__ void k_init_ev(){
    int i=blockIdx.x*blockDim.x+threadIdx.x;
    if(i<BB*EVP) g_ev[i]=1.0f;
}
__global__ void k_upass(const float* __restrict__ du, const float* __restrict__ te, int b){
    int row=blockIdx.x, t=threadIdx.x;
    if(row>NN) return;
    const float* evb=g_ev+b*EVP;
    float eds=get_eds(du,te), s=0.f;
    if(row<NN){
        const float4* E4=(const float4*)(g_E+((size_t)b*NN+row)*NN);
        const float4* v4=(const float4*)evb;
        #pragma unroll
        for(int it=0;it<8;it++){
            int i=t+it*128;
            float4 e=E4[i], w=v4[i];
            s=fmaf(e.x,w.x,s); s=fmaf(e.y,w.y,s); s=fmaf(e.z,w.z,s); s=fmaf(e.w,w.w,s);
        }
    } else for(int i=t;i<NN;i+=128) s+=evb[i];
    #pragma unroll
    for(int o=16;o;o>>=1) s+=__shfl_down_sync(~0u,s,o);
    __shared__ float ws[4];
    if((t&31)==0) ws[t>>5]=s;
    __syncthreads();
    if(t==0){
        float tot=ws[0]+ws[1]+ws[2]+ws[3];
        if(row<NN) g_eu[b*EVP+row]=1.220703125e-4f/(tot+eds*evb[NN]);
        else       g_eu[b*EVP+NN]=0.5f/(eds*tot+evb[NN]);
    }
}
__global__ void k_vpart(int b){
    int ch=blockIdx.y, n=blockIdx.x*256+threadIdx.x;
    __shared__ float su[512];
    const float* eub=g_eu+b*EVP+ch*512;
    for(int i=threadIdx.x;i<512;i+=256) su[i]=eub[i];
    __syncthreads();
    const float* Ep=g_E+((size_t)b*NN+ch*512)*NN+n;
    float acc=0.f;
    #pragma unroll 8
    for(int m=0;m<512;m++) acc=fmaf(Ep[(size_t)m*NN],su[m],acc);
    g_part[((size_t)b*8+ch)*NN+n]=acc;
}
// vfin: blocks 0..15 finish ev[0..4095]; block 16 computes the ev dustbin
__global__ void k_vfin(const float* __restrict__ du, const float* __restrict__ te, int b){
    int t=threadIdx.x;
    if(blockIdx.x==16){   // old k_vdust, bit-identical
        const float* eub=g_eu+b*EVP;
        float s=0.f;
        for(int i=t;i<NN;i+=256) s+=eub[i];
        #pragma unroll
        for(int o=16;o;o>>=1) s+=__shfl_down_sync(~0u,s,o);
        __shared__ float ws[8];
        if((t&31)==0) ws[t>>5]=s;
        __syncthreads();
        if(t==0){
            float tot=0.f;
            #pragma unroll
            for(int i=0;i<8;i++) tot+=ws[i];
            g_ev[b*EVP+NN]=0.5f/(get_eds(du,te)*tot+eub[NN]);
        }
        return;
    }
    int n=blockIdx.x*256+t;
    float s=get_eds(du,te)*g_eu[b*EVP+NN];
    #pragma unroll
    for(int ch=0;ch<8;ch++) s+=g_part[((size_t)b*8+ch)*NN+n];
    g_ev[b*EVP+n]=1.220703125e-4f/s;
}
__global__ void k_log(){
    int i=blockIdx.x*blockDim.x+threadIdx.x;
    if(i>=BB*NN) return;
    g_lu[i]=logf(g_eu[(i>>12)*EVP+(i&4095)]);
    g_lv[i]=logf(g_ev[(i>>12)*EVP+(i&4095)]);
}

// 4) row stats + top-8 over key=(z+u)+v
__device__ __forceinline__ bool better(float v1,int i1,float v2,int i2){
    return (v1>v2)||(v1==v2&&i1<i2);
}
__global__ void k_stats(const float* __restrict__ raw, const float* __restrict__ te){
    int b=blockIdx.y, m=blockIdx.x, t=threadIdx.x;
    float tv=__ldg(te), c=__frcp_rn(tv);
    float lu=g_lu[b*NN+m];
    const float* rrow=raw+((size_t)b*NN+m)*NN;
    const float* lvb=g_lv+b*NN;
    float tvv[8]; int tii[8];
    #pragma unroll
    for(int i=0;i<8;i++){tvv[i]=-FLT_MAX; tii[i]=0x7fffffff;}
    float S=0.f, ent=0.f;
    #pragma unroll 4
    for(int j=0;j<32;j++){
        int n=t+j*128;
        float z=fminf(fmaxf(divrn(rrow[n],tv,c),-50.f),50.f);
        float key=(z+lu)+lvb[n];
        float tc=fminf(fmaxf(key,-50.f),0.f);
        float P=fexp(tc);
        S+=P; ent=fmaf(P,tc,ent);
        if(key>tvv[7]){     // identical result: key<=tvv[7] never inserts
            float v=key; int id=n;
            #pragma unroll
            for(int p=0;p<8;p++){
                bool take=v>tvv[p];
                float nv=take?tvv[p]:v; int nid=take?tii[p]:id;
                tvv[p]=take?v:tvv[p]; tii[p]=take?id:tii[p];
                v=nv; id=nid;
            }
        }
    }
    float s1=S,s2=ent;
    #pragma unroll
    for(int o=16;o;o>>=1){ s1+=__shfl_down_sync(~0u,s1,o); s2+=__shfl_down_sync(~0u,s2,o); }
    __shared__ float wsS[4], wsE[4];
    if((t&31)==0){ wsS[t>>5]=s1; wsE[t>>5]=s2; }
    __shared__ float sval[1024]; __shared__ int sidx[1024];
    #pragma unroll
    for(int i=0;i<8;i++){ sval[t*8+i]=tvv[i]; sidx[t*8+i]=tii[i]; }
    __shared__ float rtv[8]; __shared__ int rti[8];
    __syncthreads();
    if(t<32){
        for(int r=0;r<8;r++){
            float bv=-FLT_MAX; int bi=0x7fffffff, bs=-1;
            for(int j=0;j<32;j++){
                int s=j*32+t;
                if(better(sval[s],sidx[s],bv,bi)){ bv=sval[s]; bi=sidx[s]; bs=s; }
            }
            #pragma unroll
            for(int o=16;o;o>>=1){
                float ov=__shfl_down_sync(~0u,bv,o);
                int oi=__shfl_down_sync(~0u,bi,o), os=__shfl_down_sync(~0u,bs,o);
                if(better(ov,oi,bv,bi)){ bv=ov; bi=oi; bs=os; }
            }
            int bs0=__shfl_sync(~0u,bs,0);
            if(t==0){ rtv[r]=bv; rti[r]=bi; sval[bs0]=-FLT_MAX; }
            __syncwarp();
        }
    }
    __syncthreads();
    size_t ro=((size_t)b*NN+m)*KK;
    if(t<8){ g_logp[ro+t]=rtv[t]; g_topi[ro+t]=rti[t]; }
    if(t==0){
        g_S[b*NN+m]=wsS[0]+wsS[1]+wsS[2]+wsS[3];
        g_ent[b*NN+m]=wsE[0]+wsE[1]+wsE[2]+wsE[3];
    }
}

// 5) gather positions / displacements
__global__ void k_geoprep(const float2* __restrict__ pA, const float2* __restrict__ pB){
    int i=blockIdx.x*blockDim.x+threadIdx.x;
    if(i>=BB*NN*KK) return;
    int k=i&7, m=(i>>3)&4095, b=i>>15;
    float2 cpos=pB[b*NN+g_topi[i]];
    g_tpos[i]=cpos;
    float2 a=pA[b*NN+m];
    g_disp[((size_t)(b*KK+k))*NN+m]=make_float2(cpos.x-a.x,cpos.y-a.y);
}

// 6) 7x7 count-exclude-pad variance -> geo
__global__ void k_geo(float* __restrict__ og){
    int bk=blockIdx.x, b=bk>>3, k=bk&7;
    __shared__ float2 sd[4096];
    for(int i=threadIdx.x;i<4096;i+=256) sd[i]=g_disp[(size_t)bk*NN+i];
    __syncthreads();
    for(int px=threadIdx.x;px<4096;px+=256){
        int y=px>>6, x=px&63;
        int y0=max(y-3,0), y1=min(y+3,63), x0=max(x-3,0), x1=min(x+3,63);
        float sx=0,sy=0,sxx=0,syy=0;
        for(int yy=y0;yy<=y1;yy++)
            for(int xx=x0;xx<=x1;xx++){
                float2 d=sd[yy*64+xx];
                sx+=d.x; sy+=d.y;
                sxx=fmaf(d.x,d.x,sxx); syy=fmaf(d.y,d.y,syy);
            }
        float inv=1.0f/(float)((y1-y0+1)*(x1-x0+1));
        float mx=sx*inv, my=sy*inv;
        float vx=fmaxf(sxx*inv-mx*mx,0.f), vy=fmaxf(syy*inv-my*my,0.f);
        og[((size_t)b*NN+px)*KK+k]=1.0f/(1.0f+(vx+vy)*100.0f);
    }
}

// 7) softmax refine + entropy
__global__ void k_final(float* __restrict__ out, const float* __restrict__ gwp){
    int row=blockIdx.x*blockDim.x+threadIdx.x;
    if(row>=BB*NN) return;
    const float* geo=out+67158016+(size_t)row*KK;
    float gw=fminf(fmaxf(__ldg(gwp),0.f),2.f);
    float cc[8], mx=-FLT_MAX;
    #pragma unroll
    for(int r=0;r<8;r++){
        float lp=fminf(fmaxf(g_logp[(size_t)row*KK+r],-50.f),50.f);
        cc[r]=lp+gw*geo[r];
        mx=fmaxf(mx,cc[r]);
    }
    float sum=0.f, w[8];
    #pragma unroll
    for(int r=0;r<8;r++){ w[r]=fexp(cc[r]-mx); sum+=w[r]; }
    float rx=0.f, ry=0.f, inv=1.0f/sum;
    #pragma unroll
    for(int r=0;r<8;r++){
        float2 p=g_tpos[(size_t)row*KK+r];
        float ww=w[r]*inv;
        rx=fmaf(ww,p.x,rx); ry=fmaf(ww,p.y,ry);
    }
    out[row*2]  =fminf(fmaxf(rx,-1.5f),1.5f);
    out[row*2+1]=fminf(fmaxf(ry,-1.5f),1.5f);
    float S=g_S[row], ent=g_ent[row];
    float rm=fmaxf(S,1e-8f);
    float plnp=ent/rm-(S/rm)*logf(rm);
    float vps=fminf(fmaxf(rm*8192.0f,0.f),1.f);
    out[32768+row]=-plnp*vps;
}

extern "C" void kernel_launch(void* const* d_in, const int* in_sizes, int n_in,
                              void* d_out, int out_size){
    const float* fa=(const float*)d_in[0];
    const float* fb=(const float*)d_in[1];
    const float2* pA=(const float2*)d_in[2];
    const float2* pB=(const float2*)d_in[3];
    const float* du=(const float*)d_in[4];
    const float* gw=(const float*)d_in[5];
    const float* te=(const float*)d_in[6];
    float* out=(float*)d_out;
    float* raw=out+49152;            // [refined 32768][entropy 16384][raw 67108864][geo 131072]
    float* geo=out+67158016;
    k_normalize<<<dim3((BB*NN*32+255)/256,2),256>>>(fa,fb);
    k_gemm<<<dim3(32,32,BB),256>>>(raw,te);
    k_init_ev<<<(BB*EVP+255)/256,256>>>();
    // batch-outer: one batch's E (67MB) stays L2-resident across its 30 passes
    for(int b=0;b<BB;b++){
        for(int it=0;it<ITERS;it++){
            k_upass<<<NN+1,128>>>(du,te,b);
            k_vpart<<<dim3(16,8),256>>>(b);
            k_vfin<<<17,256>>>(du,te,b);
        }
    }
    k_log<<<(BB*NN+255)/256,256>>>();
    k_stats<<<dim3(NN,BB),128>>>(raw,te);
    k_geoprep<<<(BB*NN*KK+255)/256,256>>>(pA,pB);
    k_geo<<<BB*KK,256>>>(geo);
    k_final<<<(BB*NN+255)/256,256>>>(out,gw);
}

// round 12
// speedup vs baseline: 1.1082x; 1.1082x over previous
#include <cuda_runtime.h>
#include <cstdint>
#include <float.h>
#include <math.h>

#define BB 4
#define NN 4096
#define CC 128
#define KK 8
#define EVP 4104
#define ITERS 15

__device__ float  g_normA[(size_t)BB*NN*CC];
__device__ float  g_normB[(size_t)BB*NN*CC];
__device__ float  g_E[(size_t)BB*NN*NN];
__device__ float  g_eu[BB*EVP];
__device__ float  g_ev[BB*EVP];
__device__ float  g_part[(size_t)BB*8*NN];
__device__ float  g_lu[BB*NN];
__device__ float  g_lv[BB*NN];
__device__ float  g_logp[(size_t)BB*NN*KK];
__device__ int    g_topi[(size_t)BB*NN*KK];
__device__ float2 g_tpos[(size_t)BB*NN*KK];
__device__ float2 g_disp[(size_t)BB*KK*NN];
__device__ float  g_S[BB*NN];
__device__ float  g_ent[BB*NN];

__device__ __forceinline__ float fexp(float x){
    float t=x*1.44269504088896341f, r=rintf(t);
    float g=fmaf(r,-0.693359375f,x); g=fmaf(r,2.12194440e-4f,g);
    float p=1.9875691500e-4f;
    p=fmaf(p,g,1.3981999507e-3f); p=fmaf(p,g,8.3334519073e-3f);
    p=fmaf(p,g,4.1665795894e-2f); p=fmaf(p,g,1.6666665459e-1f);
    p=fmaf(p,g,5.0000001201e-1f);
    return (fmaf(g*g,p,g)+1.0f)*__int_as_float(((int)r+127)<<23);
}
__device__ __forceinline__ float divrn(float x, float t, float c){
    float q=__fmul_rn(x,c), r=fmaf(-t,q,x); return fmaf(r,c,q);
}
__device__ __forceinline__ float get_eds(const float* du, const float* te){
    float tc=fminf(fmaxf(__ldg(te),0.03f),10.0f);
    return fexp(fminf(fmaxf(__fdiv_rn(__ldg(du),tc),-50.0f),50.0f));
}

// 1) L2 normalize, IEEE sqrt/div
__global__ void k_normalize(const float* __restrict__ fa, const float* __restrict__ fb){
    int w=(blockIdx.x*blockDim.x+threadIdx.x)>>5, l=threadIdx.x&31;
    if(w>=BB*NN) return;
    const float* src=(blockIdx.y?fb:fa)+(size_t)w*CC;
    float* dst=(blockIdx.y?g_normB:g_normA)+(size_t)w*CC;
    float x0=src[l],x1=src[l+32],x2=src[l+64],x3=src[l+96];
    float s=0.f;
    s=fmaf(x0,x0,s); s=fmaf(x1,x1,s); s=fmaf(x2,x2,s); s=fmaf(x3,x3,s);
    #pragma unroll
    for(int o=16;o;o>>=1) s+=__shfl_down_sync(~0u,s,o);
    s=__shfl_sync(~0u,s,0);
    float d=fmaxf(__fsqrt_rn(s),1e-12f);
    dst[l]=__fdiv_rn(x0,d); dst[l+32]=__fdiv_rn(x1,d);
    dst[l+64]=__fdiv_rn(x2,d); dst[l+96]=__fdiv_rn(x3,d);
}

// 2) SGEMM raw=A@B^T; E=exp(clip(raw/temp)). Register-prefetch of next K-tile
//    overlaps global loads with the FFMA block; FFMA order per element unchanged.
__global__ __launch_bounds__(256,2)
void k_gemm(float* __restrict__ out_raw, const float* __restrict__ tempp){
    int b=blockIdx.z, tm=blockIdx.y*128, tn=blockIdx.x*128;
    __shared__ float As[32][132], Bs[32][132];
    const float* A=g_normA+(size_t)b*NN*CC;
    const float* Bm=g_normB+(size_t)b*NN*CC;
    int tid=threadIdx.x, lr=tid>>3, lc=(tid&7)*4, tx=tid&15, ty=tid>>4;
    float acc[8][8];
    #pragma unroll
    for(int i=0;i<8;i++)
        #pragma unroll
        for(int j=0;j<8;j++) acc[i][j]=0.f;

    float4 pa[4], pb[4];
    #pragma unroll
    for(int p=0;p<4;p++){
        int r=lr+p*32;
        pa[p]=*(const float4*)(A +(size_t)(tm+r)*CC+lc);
        pb[p]=*(const float4*)(Bm+(size_t)(tn+r)*CC+lc);
    }
    #pragma unroll
    for(int step=0;step<4;step++){
        #pragma unroll
        for(int p=0;p<4;p++){
            int r=lr+p*32;
            As[lc+0][r]=pa[p].x; As[lc+1][r]=pa[p].y; As[lc+2][r]=pa[p].z; As[lc+3][r]=pa[p].w;
            Bs[lc+0][r]=pb[p].x; Bs[lc+1][r]=pb[p].y; Bs[lc+2][r]=pb[p].z; Bs[lc+3][r]=pb[p].w;
        }
        __syncthreads();
        if(step<3){
            int k0=(step+1)*32;
            #pragma unroll
            for(int p=0;p<4;p++){
                int r=lr+p*32;
                pa[p]=*(const float4*)(A +(size_t)(tm+r)*CC+k0+lc);
                pb[p]=*(const float4*)(Bm+(size_t)(tn+r)*CC+k0+lc);
            }
        }
        #pragma unroll
        for(int k=0;k<32;k++){
            float4 a0=*(const float4*)&As[k][ty*8], a1=*(const float4*)&As[k][ty*8+4];
            float4 b0=*(const float4*)&Bs[k][tx*8], b1=*(const float4*)&Bs[k][tx*8+4];
            float a[8]={a0.x,a0.y,a0.z,a0.w,a1.x,a1.y,a1.z,a1.w};
            float bf[8]={b0.x,b0.y,b0.z,b0.w,b1.x,b1.y,b1.z,b1.w};
            #pragma unroll
            for(int i=0;i<8;i++)
                #pragma unroll
                for(int j=0;j<8;j++) acc[i][j]=fmaf(a[i],bf[j],acc[i][j]);
        }
        __syncthreads();
    }
    float tv=__ldg(tempp), c=__frcp_rn(tv);
    #pragma unroll
    for(int i=0;i<8;i++){
        size_t off=((size_t)b*NN+tm+ty*8+i)*NN+tn+tx*8;
        *(float4*)(out_raw+off)  =make_float4(acc[i][0],acc[i][1],acc[i][2],acc[i][3]);
        *(float4*)(out_raw+off+4)=make_float4(acc[i][4],acc[i][5],acc[i][6],acc[i][7]);
        float e[8];
        #pragma unroll
        for(int j=0;j<8;j++){
            float z=fminf(fmaxf(divrn(acc[i][j],tv,c),-50.f),50.f);
            e[j]=fexp(z);
        }
        *(float4*)(g_E+off)  =make_float4(e[0],e[1],e[2],e[3]);
        *(float4*)(g_E+off+4)=make_float4(e[4],e[5],e[6],e[7]);
    }
}

// 3) Sinkhorn, exp domain, fp32, batch-interleaved (R9-proven 78% HBM)
__global__ void k_init_ev(){
    int i=blockIdx.x*blockDim.x+threadIdx.x;
    if(i<BB*EVP) g_ev[i]=1.0f;
}
__global__ void k_upass(const float* __restrict__ du, const float* __restrict__ te){
    int b=blockIdx.y, row=blockIdx.x, t=threadIdx.x;
    if(row>NN) return;
    const float* evb=g_ev+b*EVP;
    float eds=get_eds(du,te), s=0.f;
    if(row<NN){
        const float4* E4=(const float4*)(g_E+((size_t)b*NN+row)*NN);
        const float4* v4=(const float4*)evb;
        #pragma unroll
        for(int it=0;it<8;it++){
            int i=t+it*128;
            float4 e=E4[i], w=v4[i];
            s=fmaf(e.x,w.x,s); s=fmaf(e.y,w.y,s); s=fmaf(e.z,w.z,s); s=fmaf(e.w,w.w,s);
        }
    } else for(int i=t;i<NN;i+=128) s+=evb[i];
    #pragma unroll
    for(int o=16;o;o>>=1) s+=__shfl_down_sync(~0u,s,o);
    __shared__ float ws[4];
    if((t&31)==0) ws[t>>5]=s;
    __syncthreads();
    if(t==0){
        float tot=ws[0]+ws[1]+ws[2]+ws[3];
        if(row<NN) g_eu[b*EVP+row]=1.220703125e-4f/(tot+eds*evb[NN]);
        else       g_eu[b*EVP+NN]=0.5f/(eds*tot+evb[NN]);
    }
}
__global__ void k_vpart(){
    int b=blockIdx.z, ch=blockIdx.y, n=blockIdx.x*256+threadIdx.x;
    __shared__ float su[512];
    const float* eub=g_eu+b*EVP+ch*512;
    for(int i=threadIdx.x;i<512;i+=256) su[i]=eub[i];
    __syncthreads();
    const float* Ep=g_E+((size_t)b*NN+ch*512)*NN+n;
    float acc=0.f;
    #pragma unroll 8
    for(int m=0;m<512;m++) acc=fmaf(Ep[(size_t)m*NN],su[m],acc);
    g_part[((size_t)b*8+ch)*NN+n]=acc;
}
// vfin: blocks 0..15 finish ev[0..4095]; block 16 = ev dustbin (old vdust, bit-identical)
__global__ void k_vfin(const float* __restrict__ du, const float* __restrict__ te){
    int b=blockIdx.y, t=threadIdx.x;
    if(blockIdx.x==16){
        const float* eub=g_eu+b*EVP;
        float s=0.f;
        for(int i=t;i<NN;i+=256) s+=eub[i];
        #pragma unroll
        for(int o=16;o;o>>=1) s+=__shfl_down_sync(~0u,s,o);
        __shared__ float ws[8];
        if((t&31)==0) ws[t>>5]=s;
        __syncthreads();
        if(t==0){
            float tot=0.f;
            #pragma unroll
            for(int i=0;i<8;i++) tot+=ws[i];
            g_ev[b*EVP+NN]=0.5f/(get_eds(du,te)*tot+eub[NN]);
        }
        return;
    }
    int n=blockIdx.x*256+t;
    float s=get_eds(du,te)*g_eu[b*EVP+NN];
    #pragma unroll
    for(int ch=0;ch<8;ch++) s+=g_part[((size_t)b*8+ch)*NN+n];
    g_ev[b*EVP+n]=1.220703125e-4f/s;
}
__global__ void k_log(){
    int i=blockIdx.x*blockDim.x+threadIdx.x;
    if(i>=BB*NN) return;
    g_lu[i]=logf(g_eu[(i>>12)*EVP+(i&4095)]);
    g_lv[i]=logf(g_ev[(i>>12)*EVP+(i&4095)]);
}

// 4) row stats + top-8 over key=(z+u)+v
__device__ __forceinline__ bool better(float v1,int i1,float v2,int i2){
    return (v1>v2)||(v1==v2&&i1<i2);
}
__global__ void k_stats(const float* __restrict__ raw, const float* __restrict__ te){
    int b=blockIdx.y, m=blockIdx.x, t=threadIdx.x;
    float tv=__ldg(te), c=__frcp_rn(tv);
    float lu=g_lu[b*NN+m];
    const float* rrow=raw+((size_t)b*NN+m)*NN;
    const float* lvb=g_lv+b*NN;
    float tvv[8]; int tii[8];
    #pragma unroll
    for(int i=0;i<8;i++){tvv[i]=-FLT_MAX; tii[i]=0x7fffffff;}
    float S=0.f, ent=0.f;
    #pragma unroll 4
    for(int j=0;j<32;j++){
        int n=t+j*128;
        float z=fminf(fmaxf(divrn(rrow[n],tv,c),-50.f),50.f);
        float key=(z+lu)+lvb[n];
        float tc=fminf(fmaxf(key,-50.f),0.f);
        float P=fexp(tc);
        S+=P; ent=fmaf(P,tc,ent);
        if(key>tvv[7]){   // identical selection: key<=tvv[7] never inserts
            float v=key; int id=n;
            #pragma unroll
            for(int p=0;p<8;p++){
                bool take=v>tvv[p];
                float nv=take?tvv[p]:v; int nid=take?tii[p]:id;
                tvv[p]=take?v:tvv[p]; tii[p]=take?id:tii[p];
                v=nv; id=nid;
            }
        }
    }
    float s1=S,s2=ent;
    #pragma unroll
    for(int o=16;o;o>>=1){ s1+=__shfl_down_sync(~0u,s1,o); s2+=__shfl_down_sync(~0u,s2,o); }
    __shared__ float wsS[4], wsE[4];
    if((t&31)==0){ wsS[t>>5]=s1; wsE[t>>5]=s2; }
    __shared__ float sval[1024]; __shared__ int sidx[1024];
    #pragma unroll
    for(int i=0;i<8;i++){ sval[t*8+i]=tvv[i]; sidx[t*8+i]=tii[i]; }
    __shared__ float rtv[8]; __shared__ int rti[8];
    __syncthreads();
    if(t<32){
        for(int r=0;r<8;r++){
            float bv=-FLT_MAX; int bi=0x7fffffff, bs=-1;
            for(int j=0;j<32;j++){
                int s=j*32+t;
                if(better(sval[s],sidx[s],bv,bi)){ bv=sval[s]; bi=sidx[s]; bs=s; }
            }
            #pragma unroll
            for(int o=16;o;o>>=1){
                float ov=__shfl_down_sync(~0u,bv,o);
                int oi=__shfl_down_sync(~0u,bi,o), os=__shfl_down_sync(~0u,bs,o);
                if(better(ov,oi,bv,bi)){ bv=ov; bi=oi; bs=os; }
            }
            int bs0=__shfl_sync(~0u,bs,0);
            if(t==0){ rtv[r]=bv; rti[r]=bi; sval[bs0]=-FLT_MAX; }
            __syncwarp();
        }
    }
    __syncthreads();
    size_t ro=((size_t)b*NN+m)*KK;
    if(t<8){ g_logp[ro+t]=rtv[t]; g_topi[ro+t]=rti[t]; }
    if(t==0){
        g_S[b*NN+m]=wsS[0]+wsS[1]+wsS[2]+wsS[3];
        g_ent[b*NN+m]=wsE[0]+wsE[1]+wsE[2]+wsE[3];
    }
}

// 5) gather positions / displacements
__global__ void k_geoprep(const float2* __restrict__ pA, const float2* __restrict__ pB){
    int i=blockIdx.x*blockDim.x+threadIdx.x;
    if(i>=BB*NN*KK) return;
    int k=i&7, m=(i>>3)&4095, b=i>>15;
    float2 cpos=pB[b*NN+g_topi[i]];
    g_tpos[i]=cpos;
    float2 a=pA[b*NN+m];
    g_disp[((size_t)(b*KK+k))*NN+m]=make_float2(cpos.x-a.x,cpos.y-a.y);
}

// 6) 7x7 count-exclude-pad variance -> geo
__global__ void k_geo(float* __restrict__ og){
    int bk=blockIdx.x, b=bk>>3, k=bk&7;
    __shared__ float2 sd[4096];
    for(int i=threadIdx.x;i<4096;i+=256) sd[i]=g_disp[(size_t)bk*NN+i];
    __syncthreads();
    for(int px=threadIdx.x;px<4096;px+=256){
        int y=px>>6, x=px&63;
        int y0=max(y-3,0), y1=min(y+3,63), x0=max(x-3,0), x1=min(x+3,63);
        float sx=0,sy=0,sxx=0,syy=0;
        for(int yy=y0;yy<=y1;yy++)
            for(int xx=x0;xx<=x1;xx++){
                float2 d=sd[yy*64+xx];
                sx+=d.x; sy+=d.y;
                sxx=fmaf(d.x,d.x,sxx); syy=fmaf(d.y,d.y,syy);
            }
        float inv=1.0f/(float)((y1-y0+1)*(x1-x0+1));
        float mx=sx*inv, my=sy*inv;
        float vx=fmaxf(sxx*inv-mx*mx,0.f), vy=fmaxf(syy*inv-my*my,0.f);
        og[((size_t)b*NN+px)*KK+k]=1.0f/(1.0f+(vx+vy)*100.0f);
    }
}

// 7) softmax refine + entropy
__global__ void k_final(float* __restrict__ out, const float* __restrict__ gwp){
    int row=blockIdx.x*blockDim.x+threadIdx.x;
    if(row>=BB*NN) return;
    const float* geo=out+67158016+(size_t)row*KK;
    float gw=fminf(fmaxf(__ldg(gwp),0.f),2.f);
    float cc[8], mx=-FLT_MAX;
    #pragma unroll
    for(int r=0;r<8;r++){
        float lp=fminf(fmaxf(g_logp[(size_t)row*KK+r],-50.f),50.f);
        cc[r]=lp+gw*geo[r];
        mx=fmaxf(mx,cc[r]);
    }
    float sum=0.f, w[8];
    #pragma unroll
    for(int r=0;r<8;r++){ w[r]=fexp(cc[r]-mx); sum+=w[r]; }
    float rx=0.f, ry=0.f, inv=1.0f/sum;
    #pragma unroll
    for(int r=0;r<8;r++){
        float2 p=g_tpos[(size_t)row*KK+r];
        float ww=w[r]*inv;
        rx=fmaf(ww,p.x,rx); ry=fmaf(ww,p.y,ry);
    }
    out[row*2]  =fminf(fmaxf(rx,-1.5f),1.5f);
    out[row*2+1]=fminf(fmaxf(ry,-1.5f),1.5f);
    float S=g_S[row], ent=g_ent[row];
    float rm=fmaxf(S,1e-8f);
    float plnp=ent/rm-(S/rm)*logf(rm);
    float vps=fminf(fmaxf(rm*8192.0f,0.f),1.f);
    out[32768+row]=-plnp*vps;
}

extern "C" void kernel_launch(void* const* d_in, const int* in_sizes, int n_in,
                              void* d_out, int out_size){
    const float* fa=(const float*)d_in[0];
    const float* fb=(const float*)d_in[1];
    const float2* pA=(const float2*)d_in[2];
    const float2* pB=(const float2*)d_in[3];
    const float* du=(const float*)d_in[4];
    const float* gw=(const float*)d_in[5];
    const float* te=(const float*)d_in[6];
    float* out=(float*)d_out;
    float* raw=out+49152;            // [refined 32768][entropy 16384][raw 67108864][geo 131072]
    float* geo=out+67158016;
    k_normalize<<<dim3((BB*NN*32+255)/256,2),256>>>(fa,fb);
    k_gemm<<<dim3(32,32,BB),256>>>(raw,te);
    k_init_ev<<<(BB*EVP+255)/256,256>>>();
    for(int it=0;it<ITERS;it++){
        k_upass<<<dim3(NN+1,BB),128>>>(du,te);
        k_vpart<<<dim3(16,8,BB),256>>>();
        k_vfin<<<dim3(17,BB),256>>>(du,te);
    }
    k_log<<<(BB*NN+255)/256,256>>>();
    k_stats<<<dim3(NN,BB),128>>>(raw,te);
    k_geoprep<<<(BB*NN*KK+255)/256,256>>>(pA,pB);
    k_geo<<<BB*KK,256>>>(geo);
    k_final<<<(BB*NN+255)/256,256>>>(out,gw);
}

// round 13
// speedup vs baseline: 1.1634x; 1.0498x over previous
#include <cuda_runtime.h>
#include <cstdint>
#include <float.h>
#include <math.h>

#define BB 4
#define NN 4096
#define CC 128
#define KK 8
#define EVP 4104
#define ITERS 15

__device__ float  g_normA[(size_t)BB*NN*CC];
__device__ float  g_normB[(size_t)BB*NN*CC];
__device__ float  g_E[(size_t)BB*NN*NN];
__device__ float  g_eu[BB*EVP];
__device__ float  g_ev[BB*EVP];
__device__ float  g_part[(size_t)BB*8*NN];
__device__ float  g_lu[BB*NN];
__device__ float  g_lv[BB*NN];
__device__ float  g_logp[(size_t)BB*NN*KK];
__device__ int    g_topi[(size_t)BB*NN*KK];
__device__ float2 g_tpos[(size_t)BB*NN*KK];
__device__ float2 g_disp[(size_t)BB*KK*NN];
__device__ float  g_S[BB*NN];
__device__ float  g_ent[BB*NN];

__device__ __forceinline__ float fexp(float x){
    float t=x*1.44269504088896341f, r=rintf(t);
    float g=fmaf(r,-0.693359375f,x); g=fmaf(r,2.12194440e-4f,g);
    float p=1.9875691500e-4f;
    p=fmaf(p,g,1.3981999507e-3f); p=fmaf(p,g,8.3334519073e-3f);
    p=fmaf(p,g,4.1665795894e-2f); p=fmaf(p,g,1.6666665459e-1f);
    p=fmaf(p,g,5.0000001201e-1f);
    return (fmaf(g*g,p,g)+1.0f)*__int_as_float(((int)r+127)<<23);
}
__device__ __forceinline__ float divrn(float x, float t, float c){
    float q=__fmul_rn(x,c), r=fmaf(-t,q,x); return fmaf(r,c,q);
}
__device__ __forceinline__ float get_eds(const float* du, const float* te){
    float tc=fminf(fmaxf(__ldg(te),0.03f),10.0f);
    return fexp(fminf(fmaxf(__fdiv_rn(__ldg(du),tc),-50.0f),50.0f));
}

// 1) L2 normalize, IEEE sqrt/div
__global__ void k_normalize(const float* __restrict__ fa, const float* __restrict__ fb){
    int w=(blockIdx.x*blockDim.x+threadIdx.x)>>5, l=threadIdx.x&31;
    if(w>=BB*NN) return;
    const float* src=(blockIdx.y?fb:fa)+(size_t)w*CC;
    float* dst=(blockIdx.y?g_normB:g_normA)+(size_t)w*CC;
    float x0=src[l],x1=src[l+32],x2=src[l+64],x3=src[l+96];
    float s=0.f;
    s=fmaf(x0,x0,s); s=fmaf(x1,x1,s); s=fmaf(x2,x2,s); s=fmaf(x3,x3,s);
    #pragma unroll
    for(int o=16;o;o>>=1) s+=__shfl_down_sync(~0u,s,o);
    s=__shfl_sync(~0u,s,0);
    float d=fmaxf(__fsqrt_rn(s),1e-12f);
    dst[l]=__fdiv_rn(x0,d); dst[l+32]=__fdiv_rn(x1,d);
    dst[l+64]=__fdiv_rn(x2,d); dst[l+96]=__fdiv_rn(x3,d);
}

// 2) SGEMM raw=A@B^T; E=exp(clip(raw/temp))  — exact R9 body (no prefetch; fits 128-reg cap)
__global__ __launch_bounds__(256,2)
void k_gemm(float* __restrict__ out_raw, const float* __restrict__ tempp){
    int b=blockIdx.z, tm=blockIdx.y*128, tn=blockIdx.x*128;
    __shared__ float As[32][132], Bs[32][132];
    const float* A=g_normA+(size_t)b*NN*CC;
    const float* Bm=g_normB+(size_t)b*NN*CC;
    int tid=threadIdx.x, lr=tid>>3, lc=(tid&7)*4, tx=tid&15, ty=tid>>4;
    float acc[8][8];
    #pragma unroll
    for(int i=0;i<8;i++)
        #pragma unroll
        for(int j=0;j<8;j++) acc[i][j]=0.f;
    for(int k0=0;k0<CC;k0+=32){
        #pragma unroll
        for(int p=0;p<4;p++){
            int r=lr+p*32;
            float4 va=*(const float4*)(A +(size_t)(tm+r)*CC+k0+lc);
            float4 vb=*(const float4*)(Bm+(size_t)(tn+r)*CC+k0+lc);
            As[lc+0][r]=va.x; As[lc+1][r]=va.y; As[lc+2][r]=va.z; As[lc+3][r]=va.w;
            Bs[lc+0][r]=vb.x; Bs[lc+1][r]=vb.y; Bs[lc+2][r]=vb.z; Bs[lc+3][r]=vb.w;
        }
        __syncthreads();
        #pragma unroll
        for(int k=0;k<32;k++){
            float4 a0=*(const float4*)&As[k][ty*8], a1=*(const float4*)&As[k][ty*8+4];
            float4 b0=*(const float4*)&Bs[k][tx*8], b1=*(const float4*)&Bs[k][tx*8+4];
            float a[8]={a0.x,a0.y,a0.z,a0.w,a1.x,a1.y,a1.z,a1.w};
            float bf[8]={b0.x,b0.y,b0.z,b0.w,b1.x,b1.y,b1.z,b1.w};
            #pragma unroll
            for(int i=0;i<8;i++)
                #pragma unroll
                for(int j=0;j<8;j++) acc[i][j]=fmaf(a[i],bf[j],acc[i][j]);
        }
        __syncthreads();
    }
    float tv=__ldg(tempp), c=__frcp_rn(tv);
    #pragma unroll
    for(int i=0;i<8;i++){
        size_t off=((size_t)b*NN+tm+ty*8+i)*NN+tn+tx*8;
        *(float4*)(out_raw+off)  =make_float4(acc[i][0],acc[i][1],acc[i][2],acc[i][3]);
        *(float4*)(out_raw+off+4)=make_float4(acc[i][4],acc[i][5],acc[i][6],acc[i][7]);
        float e[8];
        #pragma unroll
        for(int j=0;j<8;j++){
            float z=fminf(fmaxf(divrn(acc[i][j],tv,c),-50.f),50.f);
            e[j]=fexp(z);
        }
        *(float4*)(g_E+off)  =make_float4(e[0],e[1],e[2],e[3]);
        *(float4*)(g_E+off+4)=make_float4(e[4],e[5],e[6],e[7]);
    }
}

// 3) Sinkhorn, exp domain, fp32, batch-interleaved (R9-proven 78% HBM)
__global__ void k_init_ev(){
    int i=blockIdx.x*blockDim.x+threadIdx.x;
    if(i<BB*EVP) g_ev[i]=1.0f;
}
__global__ void k_upass(const float* __restrict__ du, const float* __restrict__ te){
    int b=blockIdx.y, row=blockIdx.x, t=threadIdx.x;
    if(row>NN) return;
    const float* evb=g_ev+b*EVP;
    float eds=get_eds(du,te), s=0.f;
    if(row<NN){
        const float4* E4=(const float4*)(g_E+((size_t)b*NN+row)*NN);
        const float4* v4=(const float4*)evb;
        #pragma unroll
        for(int it=0;it<8;it++){
            int i=t+it*128;
            float4 e=E4[i], w=v4[i];
            s=fmaf(e.x,w.x,s); s=fmaf(e.y,w.y,s); s=fmaf(e.z,w.z,s); s=fmaf(e.w,w.w,s);
        }
    } else for(int i=t;i<NN;i+=128) s+=evb[i];
    #pragma unroll
    for(int o=16;o;o>>=1) s+=__shfl_down_sync(~0u,s,o);
    __shared__ float ws[4];
    if((t&31)==0) ws[t>>5]=s;
    __syncthreads();
    if(t==0){
        float tot=ws[0]+ws[1]+ws[2]+ws[3];
        if(row<NN) g_eu[b*EVP+row]=1.220703125e-4f/(tot+eds*evb[NN]);
        else       g_eu[b*EVP+NN]=0.5f/(eds*tot+evb[NN]);
    }
}
__global__ void k_vpart(){
    int b=blockIdx.z, ch=blockIdx.y, n=blockIdx.x*256+threadIdx.x;
    __shared__ float su[512];
    const float* eub=g_eu+b*EVP+ch*512;
    for(int i=threadIdx.x;i<512;i+=256) su[i]=eub[i];
    __syncthreads();
    const float* Ep=g_E+((size_t)b*NN+ch*512)*NN+n;
    float acc=0.f;
    #pragma unroll 8
    for(int m=0;m<512;m++) acc=fmaf(Ep[(size_t)m*NN],su[m],acc);
    g_part[((size_t)b*8+ch)*NN+n]=acc;
}
// vfin: blocks 0..15 finish ev[0..4095]; block 16 = ev dustbin (old vdust, bit-identical)
__global__ void k_vfin(const float* __restrict__ du, const float* __restrict__ te){
    int b=blockIdx.y, t=threadIdx.x;
    if(blockIdx.x==16){
        const float* eub=g_eu+b*EVP;
        float s=0.f;
        for(int i=t;i<NN;i+=256) s+=eub[i];
        #pragma unroll
        for(int o=16;o;o>>=1) s+=__shfl_down_sync(~0u,s,o);
        __shared__ float ws[8];
        if((t&31)==0) ws[t>>5]=s;
        __syncthreads();
        if(t==0){
            float tot=0.f;
            #pragma unroll
            for(int i=0;i<8;i++) tot+=ws[i];
            g_ev[b*EVP+NN]=0.5f/(get_eds(du,te)*tot+eub[NN]);
        }
        return;
    }
    int n=blockIdx.x*256+t;
    float s=get_eds(du,te)*g_eu[b*EVP+NN];
    #pragma unroll
    for(int ch=0;ch<8;ch++) s+=g_part[((size_t)b*8+ch)*NN+n];
    g_ev[b*EVP+n]=1.220703125e-4f/s;
}
__global__ void k_log(){
    int i=blockIdx.x*blockDim.x+threadIdx.x;
    if(i>=BB*NN) return;
    g_lu[i]=logf(g_eu[(i>>12)*EVP+(i&4095)]);
    g_lv[i]=logf(g_ev[(i>>12)*EVP+(i&4095)]);
}

// 4) row stats + top-8 over key=(z+u)+v
__device__ __forceinline__ bool better(float v1,int i1,float v2,int i2){
    return (v1>v2)||(v1==v2&&i1<i2);
}
__global__ void k_stats(const float* __restrict__ raw, const float* __restrict__ te){
    int b=blockIdx.y, m=blockIdx.x, t=threadIdx.x;
    float tv=__ldg(te), c=__frcp_rn(tv);
    float lu=g_lu[b*NN+m];
    const float* rrow=raw+((size_t)b*NN+m)*NN;
    const float* lvb=g_lv+b*NN;
    float tvv[8]; int tii[8];
    #pragma unroll
    for(int i=0;i<8;i++){tvv[i]=-FLT_MAX; tii[i]=0x7fffffff;}
    float S=0.f, ent=0.f;
    #pragma unroll 4
    for(int j=0;j<32;j++){
        int n=t+j*128;
        float z=fminf(fmaxf(divrn(rrow[n],tv,c),-50.f),50.f);
        float key=(z+lu)+lvb[n];
        float tc=fminf(fmaxf(key,-50.f),0.f);
        float P=fexp(tc);
        S+=P; ent=fmaf(P,tc,ent);
        if(key>tvv[7]){   // identical selection: key<=tvv[7] never inserts
            float v=key; int id=n;
            #pragma unroll
            for(int p=0;p<8;p++){
                bool take=v>tvv[p];
                float nv=take?tvv[p]:v; int nid=take?tii[p]:id;
                tvv[p]=take?v:tvv[p]; tii[p]=take?id:tii[p];
                v=nv; id=nid;
            }
        }
    }
    float s1=S,s2=ent;
    #pragma unroll
    for(int o=16;o;o>>=1){ s1+=__shfl_down_sync(~0u,s1,o); s2+=__shfl_down_sync(~0u,s2,o); }
    __shared__ float wsS[4], wsE[4];
    if((t&31)==0){ wsS[t>>5]=s1; wsE[t>>5]=s2; }
    __shared__ float sval[1024]; __shared__ int sidx[1024];
    #pragma unroll
    for(int i=0;i<8;i++){ sval[t*8+i]=tvv[i]; sidx[t*8+i]=tii[i]; }
    __shared__ float rtv[8]; __shared__ int rti[8];
    __syncthreads();
    if(t<32){
        for(int r=0;r<8;r++){
            float bv=-FLT_MAX; int bi=0x7fffffff, bs=-1;
            for(int j=0;j<32;j++){
                int s=j*32+t;
                if(better(sval[s],sidx[s],bv,bi)){ bv=sval[s]; bi=sidx[s]; bs=s; }
            }
            #pragma unroll
            for(int o=16;o;o>>=1){
                float ov=__shfl_down_sync(~0u,bv,o);
                int oi=__shfl_down_sync(~0u,bi,o), os=__shfl_down_sync(~0u,bs,o);
                if(better(ov,oi,bv,bi)){ bv=ov; bi=oi; bs=os; }
            }
            int bs0=__shfl_sync(~0u,bs,0);
            if(t==0){ rtv[r]=bv; rti[r]=bi; sval[bs0]=-FLT_MAX; }
            __syncwarp();
        }
    }
    __syncthreads();
    size_t ro=((size_t)b*NN+m)*KK;
    if(t<8){ g_logp[ro+t]=rtv[t]; g_topi[ro+t]=rti[t]; }
    if(t==0){
        g_S[b*NN+m]=wsS[0]+wsS[1]+wsS[2]+wsS[3];
        g_ent[b*NN+m]=wsE[0]+wsE[1]+wsE[2]+wsE[3];
    }
}

// 5) gather positions / displacements
__global__ void k_geoprep(const float2* __restrict__ pA, const float2* __restrict__ pB){
    int i=blockIdx.x*blockDim.x+threadIdx.x;
    if(i>=BB*NN*KK) return;
    int k=i&7, m=(i>>3)&4095, b=i>>15;
    float2 cpos=pB[b*NN+g_topi[i]];
    g_tpos[i]=cpos;
    float2 a=pA[b*NN+m];
    g_disp[((size_t)(b*KK+k))*NN+m]=make_float2(cpos.x-a.x,cpos.y-a.y);
}

// 6) 7x7 count-exclude-pad variance -> geo
__global__ void k_geo(float* __restrict__ og){
    int bk=blockIdx.x, b=bk>>3, k=bk&7;
    __shared__ float2 sd[4096];
    for(int i=threadIdx.x;i<4096;i+=256) sd[i]=g_disp[(size_t)bk*NN+i];
    __syncthreads();
    for(int px=threadIdx.x;px<4096;px+=256){
        int y=px>>6, x=px&63;
        int y0=max(y-3,0), y1=min(y+3,63), x0=max(x-3,0), x1=min(x+3,63);
        float sx=0,sy=0,sxx=0,syy=0;
        for(int yy=y0;yy<=y1;yy++)
            for(int xx=x0;xx<=x1;xx++){
                float2 d=sd[yy*64+xx];
                sx+=d.x; sy+=d.y;
                sxx=fmaf(d.x,d.x,sxx); syy=fmaf(d.y,d.y,syy);
            }
        float inv=1.0f/(float)((y1-y0+1)*(x1-x0+1));
        float mx=sx*inv, my=sy*inv;
        float vx=fmaxf(sxx*inv-mx*mx,0.f), vy=fmaxf(syy*inv-my*my,0.f);
        og[((size_t)b*NN+px)*KK+k]=1.0f/(1.0f+(vx+vy)*100.0f);
    }
}

// 7) softmax refine + entropy
__global__ void k_final(float* __restrict__ out, const float* __restrict__ gwp){
    int row=blockIdx.x*blockDim.x+threadIdx.x;
    if(row>=BB*NN) return;
    const float* geo=out+67158016+(size_t)row*KK;
    float gw=fminf(fmaxf(__ldg(gwp),0.f),2.f);
    float cc[8], mx=-FLT_MAX;
    #pragma unroll
    for(int r=0;r<8;r++){
        float lp=fminf(fmaxf(g_logp[(size_t)row*KK+r],-50.f),50.f);
        cc[r]=lp+gw*geo[r];
        mx=fmaxf(mx,cc[r]);
    }
    float sum=0.f, w[8];
    #pragma unroll
    for(int r=0;r<8;r++){ w[r]=fexp(cc[r]-mx); sum+=w[r]; }
    float rx=0.f, ry=0.f, inv=1.0f/sum;
    #pragma unroll
    for(int r=0;r<8;r++){
        float2 p=g_tpos[(size_t)row*KK+r];
        float ww=w[r]*inv;
        rx=fmaf(ww,p.x,rx); ry=fmaf(ww,p.y,ry);
    }
    out[row*2]  =fminf(fmaxf(rx,-1.5f),1.5f);
    out[row*2+1]=fminf(fmaxf(ry,-1.5f),1.5f);
    float S=g_S[row], ent=g_ent[row];
    float rm=fmaxf(S,1e-8f);
    float plnp=ent/rm-(S/rm)*logf(rm);
    float vps=fminf(fmaxf(rm*8192.0f,0.f),1.f);
    out[32768+row]=-plnp*vps;
}

extern "C" void kernel_launch(void* const* d_in, const int* in_sizes, int n_in,
                              void* d_out, int out_size){
    const float* fa=(const float*)d_in[0];
    const float* fb=(const float*)d_in[1];
    const float2* pA=(const float2*)d_in[2];
    const float2* pB=(const float2*)d_in[3];
    const float* du=(const float*)d_in[4];
    const float* gw=(const float*)d_in[5];
    const float* te=(const float*)d_in[6];
    float* out=(float*)d_out;
    float* raw=out+49152;            // [refined 32768][entropy 16384][raw 67108864][geo 131072]
    float* geo=out+67158016;
    k_normalize<<<dim3((BB*NN*32+255)/256,2),256>>>(fa,fb);
    k_gemm<<<dim3(32,32,BB),256>>>(raw,te);
    k_init_ev<<<(BB*EVP+255)/256,256>>>();
    for(int it=0;it<ITERS;it++){
        k_upass<<<dim3(NN+1,BB),128>>>(du,te);
        k_vpart<<<dim3(16,8,BB),256>>>();
        k_vfin<<<dim3(17,BB),256>>>(du,te);
    }
    k_log<<<(BB*NN+255)/256,256>>>();
    k_stats<<<dim3(NN,BB),128>>>(raw,te);
    k_geoprep<<<(BB*NN*KK+255)/256,256>>>(pA,pB);
    k_geo<<<BB*KK,256>>>(geo);
    k_final<<<(BB*NN+255)/256,256>>>(out,gw);
}

// round 14
// speedup vs baseline: 1.1691x; 1.0049x over previous
#include <cuda_runtime.h>
#include <cstdint>
#include <float.h>
#include <math.h>

#define BB 4
#define NN 4096
#define CC 128
#define KK 8
#define EVP 4104
#define ITERS 15

__device__ float  g_normA[(size_t)BB*NN*CC];
__device__ float  g_normB[(size_t)BB*NN*CC];
__device__ float  g_E[(size_t)BB*NN*NN];
__device__ float  g_eu[BB*EVP];
__device__ float  g_ev[BB*EVP];
__device__ float  g_part[(size_t)BB*8*NN];
__device__ float  g_lu[BB*NN];
__device__ float  g_lv[BB*NN];
__device__ float  g_logp[(size_t)BB*NN*KK];
__device__ int    g_topi[(size_t)BB*NN*KK];
__device__ float2 g_tpos[(size_t)BB*NN*KK];
__device__ float2 g_disp[(size_t)BB*KK*NN];
__device__ float  g_S[BB*NN];
__device__ float  g_ent[BB*NN];

__device__ __forceinline__ float fexp(float x){
    float t=x*1.44269504088896341f, r=rintf(t);
    float g=fmaf(r,-0.693359375f,x); g=fmaf(r,2.12194440e-4f,g);
    float p=1.9875691500e-4f;
    p=fmaf(p,g,1.3981999507e-3f); p=fmaf(p,g,8.3334519073e-3f);
    p=fmaf(p,g,4.1665795894e-2f); p=fmaf(p,g,1.6666665459e-1f);
    p=fmaf(p,g,5.0000001201e-1f);
    return (fmaf(g*g,p,g)+1.0f)*__int_as_float(((int)r+127)<<23);
}
__device__ __forceinline__ float divrn(float x, float t, float c){
    float q=__fmul_rn(x,c), r=fmaf(-t,q,x); return fmaf(r,c,q);
}
__device__ __forceinline__ float get_eds(const float* du, const float* te){
    float tc=fminf(fmaxf(__ldg(te),0.03f),10.0f);
    return fexp(fminf(fmaxf(__fdiv_rn(__ldg(du),tc),-50.0f),50.0f));
}

// packed dual-fp32 FMA (FFMA2): two independent IEEE-RN FMAs per issue slot.
#define FMA_F32X2(d,a,b,c) asm("fma.rn.f32x2 %0, %1, %2, %3;" : "=l"(d) : "l"(a), "l"(b), "l"(c))
#define PACK_F32X2(out,lo,hi) asm("mov.b64 %0, {%1, %2};" : "=l"(out) : "f"(lo), "f"(hi))
#define UNPACK_F32X2(lo,hi,in) asm("mov.b64 {%0, %1}, %2;" : "=f"(lo), "=f"(hi) : "l"(in))

// 1) L2 normalize, IEEE sqrt/div
__global__ void k_normalize(const float* __restrict__ fa, const float* __restrict__ fb){
    int w=(blockIdx.x*blockDim.x+threadIdx.x)>>5, l=threadIdx.x&31;
    if(w>=BB*NN) return;
    const float* src=(blockIdx.y?fb:fa)+(size_t)w*CC;
    float* dst=(blockIdx.y?g_normB:g_normA)+(size_t)w*CC;
    float x0=src[l],x1=src[l+32],x2=src[l+64],x3=src[l+96];
    float s=0.f;
    s=fmaf(x0,x0,s); s=fmaf(x1,x1,s); s=fmaf(x2,x2,s); s=fmaf(x3,x3,s);
    #pragma unroll
    for(int o=16;o;o>>=1) s+=__shfl_down_sync(~0u,s,o);
    s=__shfl_sync(~0u,s,0);
    float d=fmaxf(__fsqrt_rn(s),1e-12f);
    dst[l]=__fdiv_rn(x0,d); dst[l+32]=__fdiv_rn(x1,d);
    dst[l+64]=__fdiv_rn(x2,d); dst[l+96]=__fdiv_rn(x3,d);
}

// 2) SGEMM raw=A@B^T via packed f32x2 FMA (bit-identical to scalar FFMA chain);
//    E=exp(clip(raw/temp)) epilogue unchanged.
__global__ __launch_bounds__(256,2)
void k_gemm(float* __restrict__ out_raw, const float* __restrict__ tempp){
    int b=blockIdx.z, tm=blockIdx.y*128, tn=blockIdx.x*128;
    __shared__ float As[32][132], Bs[32][132];
    const float* A=g_normA+(size_t)b*NN*CC;
    const float* Bm=g_normB+(size_t)b*NN*CC;
    int tid=threadIdx.x, lr=tid>>3, lc=(tid&7)*4, tx=tid&15, ty=tid>>4;
    unsigned long long acc2[8][4];
    #pragma unroll
    for(int i=0;i<8;i++)
        #pragma unroll
        for(int j=0;j<4;j++) acc2[i][j]=0ull;
    for(int k0=0;k0<CC;k0+=32){
        #pragma unroll
        for(int p=0;p<4;p++){
            int r=lr+p*32;
            float4 va=*(const float4*)(A +(size_t)(tm+r)*CC+k0+lc);
            float4 vb=*(const float4*)(Bm+(size_t)(tn+r)*CC+k0+lc);
            As[lc+0][r]=va.x; As[lc+1][r]=va.y; As[lc+2][r]=va.z; As[lc+3][r]=va.w;
            Bs[lc+0][r]=vb.x; Bs[lc+1][r]=vb.y; Bs[lc+2][r]=vb.z; Bs[lc+3][r]=vb.w;
        }
        __syncthreads();
        #pragma unroll
        for(int k=0;k<32;k++){
            float4 a0=*(const float4*)&As[k][ty*8], a1=*(const float4*)&As[k][ty*8+4];
            // B pairs read pre-packed: consecutive floats as u64 = (b_j, b_{j+1})
            ulonglong2 bq0=*(const ulonglong2*)&Bs[k][tx*8];
            ulonglong2 bq1=*(const ulonglong2*)&Bs[k][tx*8+4];
            unsigned long long bp0=bq0.x, bp1=bq0.y, bp2=bq1.x, bp3=bq1.y;
            float av[8]={a0.x,a0.y,a0.z,a0.w,a1.x,a1.y,a1.z,a1.w};
            #pragma unroll
            for(int i=0;i<8;i++){
                unsigned long long ap;
                PACK_F32X2(ap, av[i], av[i]);
                FMA_F32X2(acc2[i][0], ap, bp0, acc2[i][0]);
                FMA_F32X2(acc2[i][1], ap, bp1, acc2[i][1]);
                FMA_F32X2(acc2[i][2], ap, bp2, acc2[i][2]);
                FMA_F32X2(acc2[i][3], ap, bp3, acc2[i][3]);
            }
        }
        __syncthreads();
    }
    float tv=__ldg(tempp), c=__frcp_rn(tv);
    #pragma unroll
    for(int i=0;i<8;i++){
        size_t off=((size_t)b*NN+tm+ty*8+i)*NN+tn+tx*8;
        float acc[8];
        #pragma unroll
        for(int j=0;j<4;j++) UNPACK_F32X2(acc[2*j], acc[2*j+1], acc2[i][j]);
        *(float4*)(out_raw+off)  =make_float4(acc[0],acc[1],acc[2],acc[3]);
        *(float4*)(out_raw+off+4)=make_float4(acc[4],acc[5],acc[6],acc[7]);
        float e[8];
        #pragma unroll
        for(int j=0;j<8;j++){
            float z=fminf(fmaxf(divrn(acc[j],tv,c),-50.f),50.f);
            e[j]=fexp(z);
        }
        *(float4*)(g_E+off)  =make_float4(e[0],e[1],e[2],e[3]);
        *(float4*)(g_E+off+4)=make_float4(e[4],e[5],e[6],e[7]);
    }
}

// 3) Sinkhorn, exp domain, fp32, batch-interleaved (R9-proven 78% HBM)
__global__ void k_init_ev(){
    int i=blockIdx.x*blockDim.x+threadIdx.x;
    if(i<BB*EVP) g_ev[i]=1.0f;
}
__global__ void k_upass(const float* __restrict__ du, const float* __restrict__ te){
    int b=blockIdx.y, row=blockIdx.x, t=threadIdx.x;
    if(row>NN) return;
    const float* evb=g_ev+b*EVP;
    float eds=get_eds(du,te), s=0.f;
    if(row<NN){
        const float4* E4=(const float4*)(g_E+((size_t)b*NN+row)*NN);
        const float4* v4=(const float4*)evb;
        #pragma unroll
        for(int it=0;it<8;it++){
            int i=t+it*128;
            float4 e=E4[i], w=v4[i];
            s=fmaf(e.x,w.x,s); s=fmaf(e.y,w.y,s); s=fmaf(e.z,w.z,s); s=fmaf(e.w,w.w,s);
        }
    } else for(int i=t;i<NN;i+=128) s+=evb[i];
    #pragma unroll
    for(int o=16;o;o>>=1) s+=__shfl_down_sync(~0u,s,o);
    __shared__ float ws[4];
    if((t&31)==0) ws[t>>5]=s;
    __syncthreads();
    if(t==0){
        float tot=ws[0]+ws[1]+ws[2]+ws[3];
        if(row<NN) g_eu[b*EVP+row]=1.220703125e-4f/(tot+eds*evb[NN]);
        else       g_eu[b*EVP+NN]=0.5f/(eds*tot+evb[NN]);
    }
}
__global__ void k_vpart(){
    int b=blockIdx.z, ch=blockIdx.y, n=blockIdx.x*256+threadIdx.x;
    __shared__ float su[512];
    const float* eub=g_eu+b*EVP+ch*512;
    for(int i=threadIdx.x;i<512;i+=256) su[i]=eub[i];
    __syncthreads();
    const float* Ep=g_E+((size_t)b*NN+ch*512)*NN+n;
    float acc=0.f;
    #pragma unroll 8
    for(int m=0;m<512;m++) acc=fmaf(Ep[(size_t)m*NN],su[m],acc);
    g_part[((size_t)b*8+ch)*NN+n]=acc;
}
// vfin: blocks 0..15 finish ev[0..4095]; block 16 = ev dustbin
__global__ void k_vfin(const float* __restrict__ du, const float* __restrict__ te){
    int b=blockIdx.y, t=threadIdx.x;
    if(blockIdx.x==16){
        const float* eub=g_eu+b*EVP;
        float s=0.f;
        for(int i=t;i<NN;i+=256) s+=eub[i];
        #pragma unroll
        for(int o=16;o;o>>=1) s+=__shfl_down_sync(~0u,s,o);
        __shared__ float ws[8];
        if((t&31)==0) ws[t>>5]=s;
        __syncthreads();
        if(t==0){
            float tot=0.f;
            #pragma unroll
            for(int i=0;i<8;i++) tot+=ws[i];
            g_ev[b*EVP+NN]=0.5f/(get_eds(du,te)*tot+eub[NN]);
        }
        return;
    }
    int n=blockIdx.x*256+t;
    float s=get_eds(du,te)*g_eu[b*EVP+NN];
    #pragma unroll
    for(int ch=0;ch<8;ch++) s+=g_part[((size_t)b*8+ch)*NN+n];
    g_ev[b*EVP+n]=1.220703125e-4f/s;
}
__global__ void k_log(){
    int i=blockIdx.x*blockDim.x+threadIdx.x;
    if(i>=BB*NN) return;
    g_lu[i]=logf(g_eu[(i>>12)*EVP+(i&4095)]);
    g_lv[i]=logf(g_ev[(i>>12)*EVP+(i&4095)]);
}

// 4) row stats + top-8 over key=(z+u)+v
__device__ __forceinline__ bool better(float v1,int i1,float v2,int i2){
    return (v1>v2)||(v1==v2&&i1<i2);
}
__global__ void k_stats(const float* __restrict__ raw, const float* __restrict__ te){
    int b=blockIdx.y, m=blockIdx.x, t=threadIdx.x;
    float tv=__ldg(te), c=__frcp_rn(tv);
    float lu=g_lu[b*NN+m];
    const float* rrow=raw+((size_t)b*NN+m)*NN;
    const float* lvb=g_lv+b*NN;
    float tvv[8]; int tii[8];
    #pragma unroll
    for(int i=0;i<8;i++){tvv[i]=-FLT_MAX; tii[i]=0x7fffffff;}
    float S=0.f, ent=0.f;
    #pragma unroll 4
    for(int j=0;j<32;j++){
        int n=t+j*128;
        float z=fminf(fmaxf(divrn(rrow[n],tv,c),-50.f),50.f);
        float key=(z+lu)+lvb[n];
        float tc=fminf(fmaxf(key,-50.f),0.f);
        float P=fexp(tc);
        S+=P; ent=fmaf(P,tc,ent);
        if(key>tvv[7]){
            float v=key; int id=n;
            #pragma unroll
            for(int p=0;p<8;p++){
                bool take=v>tvv[p];
                float nv=take?tvv[p]:v; int nid=take?tii[p]:id;
                tvv[p]=take?v:tvv[p]; tii[p]=take?id:tii[p];
                v=nv; id=nid;
            }
        }
    }
    float s1=S,s2=ent;
    #pragma unroll
    for(int o=16;o;o>>=1){ s1+=__shfl_down_sync(~0u,s1,o); s2+=__shfl_down_sync(~0u,s2,o); }
    __shared__ float wsS[4], wsE[4];
    if((t&31)==0){ wsS[t>>5]=s1; wsE[t>>5]=s2; }
    __shared__ float sval[1024]; __shared__ int sidx[1024];
    #pragma unroll
    for(int i=0;i<8;i++){ sval[t*8+i]=tvv[i]; sidx[t*8+i]=tii[i]; }
    __shared__ float rtv[8]; __shared__ int rti[8];
    __syncthreads();
    if(t<32){
        for(int r=0;r<8;r++){
            float bv=-FLT_MAX; int bi=0x7fffffff, bs=-1;
            for(int j=0;j<32;j++){
                int s=j*32+t;
                if(better(sval[s],sidx[s],bv,bi)){ bv=sval[s]; bi=sidx[s]; bs=s; }
            }
            #pragma unroll
            for(int o=16;o;o>>=1){
                float ov=__shfl_down_sync(~0u,bv,o);
                int oi=__shfl_down_sync(~0u,bi,o), os=__shfl_down_sync(~0u,bs,o);
                if(better(ov,oi,bv,bi)){ bv=ov; bi=oi; bs=os; }
            }
            int bs0=__shfl_sync(~0u,bs,0);
            if(t==0){ rtv[r]=bv; rti[r]=bi; sval[bs0]=-FLT_MAX; }
            __syncwarp();
        }
    }
    __syncthreads();
    size_t ro=((size_t)b*NN+m)*KK;
    if(t<8){ g_logp[ro+t]=rtv[t]; g_topi[ro+t]=rti[t]; }
    if(t==0){
        g_S[b*NN+m]=wsS[0]+wsS[1]+wsS[2]+wsS[3];
        g_ent[b*NN+m]=wsE[0]+wsE[1]+wsE[2]+wsE[3];
    }
}

// 5) gather positions / displacements
__global__ void k_geoprep(const float2* __restrict__ pA, const float2* __restrict__ pB){
    int i=blockIdx.x*blockDim.x+threadIdx.x;
    if(i>=BB*NN*KK) return;
    int k=i&7, m=(i>>3)&4095, b=i>>15;
    float2 cpos=pB[b*NN+g_topi[i]];
    g_tpos[i]=cpos;
    float2 a=pA[b*NN+m];
    g_disp[((size_t)(b*KK+k))*NN+m]=make_float2(cpos.x-a.x,cpos.y-a.y);
}

// 6) 7x7 count-exclude-pad variance -> geo
__global__ void k_geo(float* __restrict__ og){
    int bk=blockIdx.x, b=bk>>3, k=bk&7;
    __shared__ float2 sd[4096];
    for(int i=threadIdx.x;i<4096;i+=256) sd[i]=g_disp[(size_t)bk*NN+i];
    __syncthreads();
    for(int px=threadIdx.x;px<4096;px+=256){
        int y=px>>6, x=px&63;
        int y0=max(y-3,0), y1=min(y+3,63), x0=max(x-3,0), x1=min(x+3,63);
        float sx=0,sy=0,sxx=0,syy=0;
        for(int yy=y0;yy<=y1;yy++)
            for(int xx=x0;xx<=x1;xx++){
                float2 d=sd[yy*64+xx];
                sx+=d.x; sy+=d.y;
                sxx=fmaf(d.x,d.x,sxx); syy=fmaf(d.y,d.y,syy);
            }
        float inv=1.0f/(float)((y1-y0+1)*(x1-x0+1));
        float mx=sx*inv, my=sy*inv;
        float vx=fmaxf(sxx*inv-mx*mx,0.f), vy=fmaxf(syy*inv-my*my,0.f);
        og[((size_t)b*NN+px)*KK+k]=1.0f/(1.0f+(vx+vy)*100.0f);
    }
}

// 7) softmax refine + entropy
__global__ void k_final(float* __restrict__ out, const float* __restrict__ gwp){
    int row=blockIdx.x*blockDim.x+threadIdx.x;
    if(row>=BB*NN) return;
    const float* geo=out+67158016+(size_t)row*KK;
    float gw=fminf(fmaxf(__ldg(gwp),0.f),2.f);
    float cc[8], mx=-FLT_MAX;
    #pragma unroll
    for(int r=0;r<8;r++){
        float lp=fminf(fmaxf(g_logp[(size_t)row*KK+r],-50.f),50.f);
        cc[r]=lp+gw*geo[r];
        mx=fmaxf(mx,cc[r]);
    }
    float sum=0.f, w[8];
    #pragma unroll
    for(int r=0;r<8;r++){ w[r]=fexp(cc[r]-mx); sum+=w[r]; }
    float rx=0.f, ry=0.f, inv=1.0f/sum;
    #pragma unroll
    for(int r=0;r<8;r++){
        float2 p=g_tpos[(size_t)row*KK+r];
        float ww=w[r]*inv;
        rx=fmaf(ww,p.x,rx); ry=fmaf(ww,p.y,ry);
    }
    out[row*2]  =fminf(fmaxf(rx,-1.5f),1.5f);
    out[row*2+1]=fminf(fmaxf(ry,-1.5f),1.5f);
    float S=g_S[row], ent=g_ent[row];
    float rm=fmaxf(S,1e-8f);
    float plnp=ent/rm-(S/rm)*logf(rm);
    float vps=fminf(fmaxf(rm*8192.0f,0.f),1.f);
    out[32768+row]=-plnp*vps;
}

extern "C" void kernel_launch(void* const* d_in, const int* in_sizes, int n_in,
                              void* d_out, int out_size){
    const float* fa=(const float*)d_in[0];
    const float* fb=(const float*)d_in[1];
    const float2* pA=(const float2*)d_in[2];
    const float2* pB=(const float2*)d_in[3];
    const float* du=(const float*)d_in[4];
    const float* gw=(const float*)d_in[5];
    const float* te=(const float*)d_in[6];
    float* out=(float*)d_out;
    float* raw=out+49152;            // [refined 32768][entropy 16384][raw 67108864][geo 131072]
    float* geo=out+67158016;
    k_normalize<<<dim3((BB*NN*32+255)/256,2),256>>>(fa,fb);
    k_gemm<<<dim3(32,32,BB),256>>>(raw,te);
    k_init_ev<<<(BB*EVP+255)/256,256>>>();
    for(int it=0;it<ITERS;it++){
        k_upass<<<dim3(NN+1,BB),128>>>(du,te);
        k_vpart<<<dim3(16,8,BB),256>>>();
        k_vfin<<<dim3(17,BB),256>>>(du,te);
    }
    k_log<<<(BB*NN+255)/256,256>>>();
    k_stats<<<dim3(NN,BB),128>>>(raw,te);
    k_geoprep<<<(BB*NN*KK+255)/256,256>>>(pA,pB);
    k_geo<<<BB*KK,256>>>(geo);
    k_final<<<(BB*NN+255)/256,256>>>(out,gw);
}